// round 17
// baseline (speedup 1.0000x reference)
#include <cuda_runtime.h>
#include <cuda_fp16.h>
#include <cstdint>
#include <cstddef>

// ---------------------------------------------------------------------------
// y[8192, 11008] = x[8192,4096] @ (W_int8 * group_scales)^T + bias.
// dtypes (confirmed): x f32, W int32(int8), scales f32, bias f32, out f32.
// sm_103 (no 'a'): tcgen05 unavailable -> mma.sync HMMA (measured rt=8).
// Pass 0 (fused): x f32 -> fp16 scratch AND dequant W -> fp16 scratch.
// Pass 1: 128x128x64 GEMM, warp tile 64x32, ldmatrix, occupancy 2, 3-stage
//         cp.async pipeline. ROUND-17: per-kc __syncthreads replaced by a
//         named-barrier arrive/wait split (bar.arrive 1,512 after the last
//         LDSM of the stage + cp.async.wait; bar.sync 1,512 after the tail
//         MMAs) so barrier convergence overlaps tensor work. Stage-disjoint
//         overwrite (+1 full iteration of slack) makes the early arrive safe.
// ---------------------------------------------------------------------------

static constexpr int IN_F   = 4096;
static constexpr int OUT_F  = 11008;
static constexpr int M_TOT  = 8192;
static constexpr int GROUPS = 32;

static constexpr int BM = 128;
static constexpr int BN = 128;
static constexpr int BK = 64;
static constexpr int NSTG = 3;
static constexpr int KITERS = IN_F / BK;        // 64
static constexpr int MTILES = M_TOT / BM;       // 64
static constexpr int NTILES = OUT_F / BN;       // 86

static constexpr int ROW_BYTES = (BK + 8) * 2;  // 144 B row stride (conflict-free)
static constexpr int A_BYTES = BM * ROW_BYTES;  // 18432
static constexpr int B_BYTES = BN * ROW_BYTES;  // 18432
static constexpr int STG_BYTES = A_BYTES + B_BYTES;  // 36864
static constexpr int B_OFF = A_BYTES;
static constexpr int BIAS_OFF = NSTG * STG_BYTES;    // 110592
static constexpr int SM_TOTAL = BIAS_OFF + 512;      // 111104 -> 2 CTAs/SM

__device__ __half g_wdq[(size_t)OUT_F * IN_F];  // fp16 dequant scratch (~86 MB)
__device__ __half g_xh[(size_t)M_TOT * IN_F];   // fp16 x scratch (~64 MB)

// ---------------- Pass 0: fused x-convert + W-dequant -----------------------

static constexpr unsigned XH_BLOCKS = (unsigned)((size_t)M_TOT * IN_F / 2048);  // 16384
static constexpr unsigned DQ_BLOCKS = (unsigned)((size_t)OUT_F * IN_F / 2048);  // 22016

__global__ void prep_kernel(const float* __restrict__ x, const int* __restrict__ w,
                            const float* __restrict__ sc) {
    const unsigned b = blockIdx.x;
    if (b < XH_BLOCKS) {
        size_t t = (size_t)b * blockDim.x + threadIdx.x;
        size_t e = t * 8;
        const float4* x4 = reinterpret_cast<const float4*>(x + e);
        float4 v0 = x4[0];
        float4 v1 = x4[1];
        __half h[8];
        h[0] = __float2half_rn(v0.x); h[1] = __float2half_rn(v0.y);
        h[2] = __float2half_rn(v0.z); h[3] = __float2half_rn(v0.w);
        h[4] = __float2half_rn(v1.x); h[5] = __float2half_rn(v1.y);
        h[6] = __float2half_rn(v1.z); h[7] = __float2half_rn(v1.w);
        *reinterpret_cast<uint4*>(&g_xh[e]) = *reinterpret_cast<const uint4*>(h);
    } else {
        size_t t = (size_t)(b - XH_BLOCKS) * blockDim.x + threadIdx.x;
        size_t e = t * 8;
        const int4* w4 = reinterpret_cast<const int4*>(w + e);
        int4 q0 = w4[0];
        int4 q1 = w4[1];
        int o = (int)(e >> 12);
        int g = ((int)e & 4095) >> 7;
        float s = sc[o * GROUPS + g];
        __half h[8];
        h[0] = __float2half_rn(s * (float)q0.x); h[1] = __float2half_rn(s * (float)q0.y);
        h[2] = __float2half_rn(s * (float)q0.z); h[3] = __float2half_rn(s * (float)q0.w);
        h[4] = __float2half_rn(s * (float)q1.x); h[5] = __float2half_rn(s * (float)q1.y);
        h[6] = __float2half_rn(s * (float)q1.z); h[7] = __float2half_rn(s * (float)q1.w);
        *reinterpret_cast<uint4*>(&g_wdq[e]) = *reinterpret_cast<const uint4*>(h);
    }
}

// ---------------- Pass 1: HMMA GEMM ----------------------------------------

#define CP_ASYNC16(sm, gm) \
    asm volatile("cp.async.cg.shared.global [%0], [%1], 16;" :: "r"(sm), "l"(gm))
#define CP_COMMIT() asm volatile("cp.async.commit_group;" ::: "memory")
#define CP_WAIT1()  asm volatile("cp.async.wait_group 1;"  ::: "memory")

// Named-barrier split: all 256 threads arrive once AND sync once per phase
// -> expected count 512. Release overlaps the tail MMAs issued in between.
#define BAR_ARRIVE_1() asm volatile("bar.arrive 1, 512;" ::: "memory")
#define BAR_SYNC_1()   asm volatile("bar.sync 1, 512;"   ::: "memory")

#define LDSM4(r0, r1, r2, r3, addr) \
    asm volatile("ldmatrix.sync.aligned.m8n8.x4.shared.b16 {%0,%1,%2,%3}, [%4];" \
        : "=r"(r0), "=r"(r1), "=r"(r2), "=r"(r3) : "r"(addr))

__device__ __forceinline__ uint32_t smem_u32(const void* p) {
    uint32_t a;
    asm("{ .reg .u64 t; cvta.to.shared.u64 t, %1; cvt.u32.u64 %0, t; }"
        : "=r"(a) : "l"(p));
    return a;
}

__device__ __forceinline__ void mma16816(float c[4], uint32_t a0, uint32_t a1,
                                         uint32_t a2, uint32_t a3,
                                         uint32_t b0, uint32_t b1) {
    asm volatile(
        "mma.sync.aligned.m16n8k16.row.col.f32.f16.f16.f32 "
        "{%0,%1,%2,%3}, {%4,%5,%6,%7}, {%8,%9}, {%0,%1,%2,%3};"
        : "+f"(c[0]), "+f"(c[1]), "+f"(c[2]), "+f"(c[3])
        : "r"(a0), "r"(a1), "r"(a2), "r"(a3), "r"(b0), "r"(b1));
}

__global__ void __launch_bounds__(256, 2)
gemm_kernel(const float* __restrict__ bias, float* __restrict__ out) {
    extern __shared__ __align__(16) char smem[];
    const uint32_t sb = smem_u32(smem);
    const int tid = threadIdx.x;
    const int wid = tid >> 5;
    const int lane = tid & 31;
    const int g = lane >> 2;
    const int t = lane & 3;

    const int bid = blockIdx.x;
    const int mi = bid & (MTILES - 1);   // M fastest: W N-band + x stay L2-hot
    const int ni = bid >> 6;
    const int m0 = mi * BM;
    const int n0 = ni * BN;

    const int wm = (wid >> 2) * 64;
    const int wn = (wid & 3) * 32;

    // ---- cp.async slots: 4 A + 4 B chunks of 16B per thread/stage
    const char* gA[4]; uint32_t sA[4];
    const char* gB[4]; uint32_t sB[4];
    #pragma unroll
    for (int r = 0; r < 4; r++) {
        int chunk = r * 256 + tid;
        int row = chunk >> 3, seg = chunk & 7;
        gA[r] = reinterpret_cast<const char*>(g_xh + (size_t)(m0 + row) * IN_F) + seg * 16;
        sA[r] = (uint32_t)(row * ROW_BYTES + seg * 16);
        gB[r] = reinterpret_cast<const char*>(g_wdq + (size_t)(n0 + row) * IN_F) + seg * 16;
        sB[r] = (uint32_t)(B_OFF + row * ROW_BYTES + seg * 16);
    }

    auto load_stage = [&](int kc) {
        const uint32_t so = (uint32_t)((kc % NSTG) * STG_BYTES);
        const size_t ko = (size_t)kc * (BK * 2);
        #pragma unroll
        for (int r = 0; r < 4; r++) {
            CP_ASYNC16(sb + so + sA[r], gA[r] + ko);
            CP_ASYNC16(sb + so + sB[r], gB[r] + ko);
        }
    };

    // ---- ldmatrix per-lane base addresses (within a stage)
    uint32_t aAd[4];
    #pragma unroll
    for (int i = 0; i < 4; i++)
        aAd[i] = (uint32_t)((wm + i * 16 + (lane & 15)) * ROW_BYTES + (lane >> 4) * 16);
    uint32_t bAd[2];
    {
        const int q = lane >> 3, lr = lane & 7;
        const int rowoff = ((q >> 1) << 3) + lr;
        const int colb = (q & 1) * 16;
        #pragma unroll
        for (int jp = 0; jp < 2; jp++)
            bAd[jp] = (uint32_t)(B_OFF + (wn + jp * 16 + rowoff) * ROW_BYTES + colb);
    }

    float acc[4][4][4];
    #pragma unroll
    for (int i = 0; i < 4; i++)
        #pragma unroll
        for (int j = 0; j < 4; j++)
            #pragma unroll
            for (int q = 0; q < 4; q++) acc[i][j][q] = 0.0f;

    // ---- bias -> smem (once)
    if (tid < 128)
        reinterpret_cast<float*>(smem + BIAS_OFF)[tid] = bias[n0 + tid];

    // ---- prologue: fill 2 of 3 stages; one full barrier for visibility
    load_stage(0); CP_COMMIT();
    load_stage(1); CP_COMMIT();
    CP_WAIT1();                // stage 0 complete (own groups)
    __syncthreads();           // publish stage 0 + bias to all warps

    #pragma unroll 1
    for (int kc = 0; kc < KITERS; ++kc) {
        const uint32_t stg = sb + (uint32_t)((kc % NSTG) * STG_BYTES);

        // -- fragment preloads FIRST
        uint32_t ab[2][4];
        uint32_t bb[2][8];
        #pragma unroll
        for (int jp = 0; jp < 2; jp++)
            LDSM4(bb[0][jp * 4 + 0], bb[0][jp * 4 + 1],
                  bb[0][jp * 4 + 2], bb[0][jp * 4 + 3], stg + bAd[jp]);
        LDSM4(ab[0][0], ab[0][1], ab[0][2], ab[0][3], stg + aAd[0]);

        // -- ks = 0 (peeled): MMAs start before any cp.async issue
        {
            uint32_t* bc = bb[0];
            uint32_t* bn = bb[1];
            #pragma unroll
            for (int jp = 0; jp < 2; jp++)
                LDSM4(bn[jp * 4 + 0], bn[jp * 4 + 1],
                      bn[jp * 4 + 2], bn[jp * 4 + 3], stg + bAd[jp] + 32);
            #pragma unroll
            for (int i = 0; i < 4; i++) {
                uint32_t* ac = ab[i & 1];
                uint32_t* an = ab[(i + 1) & 1];
                if (i < 3) {
                    LDSM4(an[0], an[1], an[2], an[3], stg + aAd[i + 1]);
                } else {
                    LDSM4(an[0], an[1], an[2], an[3], stg + aAd[0] + 32);
                }
                mma16816(acc[i][0], ac[0], ac[1], ac[2], ac[3], bc[0], bc[1]);
                mma16816(acc[i][1], ac[0], ac[1], ac[2], ac[3], bc[2], bc[3]);
                mma16816(acc[i][2], ac[0], ac[1], ac[2], ac[3], bc[4], bc[5]);
                mma16816(acc[i][3], ac[0], ac[1], ac[2], ac[3], bc[6], bc[7]);
            }
        }

        // -- deferred producer: fill stage kc+2 (overwrites stage kc-1;
        //    safe: this point is after the top sync of iteration kc, which
        //    required all warps' arrives — issued after their stage kc-1 reads)
        if (kc + 2 < KITERS) load_stage(kc + 2);
        CP_COMMIT();           // exactly one commit per iteration

        // -- ks = 1..2 (generic, with B prefetch of next ks)
        #pragma unroll
        for (int ks = 1; ks < 3; ks++) {
            const uint32_t ko = (uint32_t)(ks * 32);
            uint32_t* bc = bb[ks & 1];
            uint32_t* bn = bb[(ks + 1) & 1];
            #pragma unroll
            for (int jp = 0; jp < 2; jp++)
                LDSM4(bn[jp * 4 + 0], bn[jp * 4 + 1],
                      bn[jp * 4 + 2], bn[jp * 4 + 3],
                      stg + bAd[jp] + ko + 32);
            #pragma unroll
            for (int i = 0; i < 4; i++) {
                uint32_t* ac = ab[i & 1];
                uint32_t* an = ab[(i + 1) & 1];
                if (i < 3) {
                    LDSM4(an[0], an[1], an[2], an[3], stg + aAd[i + 1] + ko);
                } else {
                    LDSM4(an[0], an[1], an[2], an[3], stg + aAd[0] + ko + 32);
                }
                mma16816(acc[i][0], ac[0], ac[1], ac[2], ac[3], bc[0], bc[1]);
                mma16816(acc[i][1], ac[0], ac[1], ac[2], ac[3], bc[2], bc[3]);
                mma16816(acc[i][2], ac[0], ac[1], ac[2], ac[3], bc[4], bc[5]);
                mma16816(acc[i][3], ac[0], ac[1], ac[2], ac[3], bc[6], bc[7]);
            }
        }

        // -- ks = 3 (peeled): early arrive after the LAST LDSM of stage kc,
        //    tail MMAs run inside the arrive->sync window
        {
            const uint32_t ko = 96;
            uint32_t* bc = bb[1];
            // i = 0
            LDSM4(ab[1][0], ab[1][1], ab[1][2], ab[1][3], stg + aAd[1] + ko);
            mma16816(acc[0][0], ab[0][0], ab[0][1], ab[0][2], ab[0][3], bc[0], bc[1]);
            mma16816(acc[0][1], ab[0][0], ab[0][1], ab[0][2], ab[0][3], bc[2], bc[3]);
            mma16816(acc[0][2], ab[0][0], ab[0][1], ab[0][2], ab[0][3], bc[4], bc[5]);
            mma16816(acc[0][3], ab[0][0], ab[0][1], ab[0][2], ab[0][3], bc[6], bc[7]);
            // i = 1
            LDSM4(ab[0][0], ab[0][1], ab[0][2], ab[0][3], stg + aAd[2] + ko);
            mma16816(acc[1][0], ab[1][0], ab[1][1], ab[1][2], ab[1][3], bc[0], bc[1]);
            mma16816(acc[1][1], ab[1][0], ab[1][1], ab[1][2], ab[1][3], bc[2], bc[3]);
            mma16816(acc[1][2], ab[1][0], ab[1][1], ab[1][2], ab[1][3], bc[4], bc[5]);
            mma16816(acc[1][3], ab[1][0], ab[1][1], ab[1][2], ab[1][3], bc[6], bc[7]);
            // i = 2 — contains the last smem read of stage kc
            LDSM4(ab[1][0], ab[1][1], ab[1][2], ab[1][3], stg + aAd[3] + ko);
            mma16816(acc[2][0], ab[0][0], ab[0][1], ab[0][2], ab[0][3], bc[0], bc[1]);
            mma16816(acc[2][1], ab[0][0], ab[0][1], ab[0][2], ab[0][3], bc[2], bc[3]);
            mma16816(acc[2][2], ab[0][0], ab[0][1], ab[0][2], ab[0][3], bc[4], bc[5]);
            mma16816(acc[2][3], ab[0][0], ab[0][1], ab[0][2], ab[0][3], bc[6], bc[7]);
            // early handoff: own stage-(kc+1) copies done + my reads done
            if (kc + 1 < KITERS) {
                CP_WAIT1();
                BAR_ARRIVE_1();
            }
            // i = 3 — register-only tail, overlaps other warps' barrier wait
            mma16816(acc[3][0], ab[1][0], ab[1][1], ab[1][2], ab[1][3], bc[0], bc[1]);
            mma16816(acc[3][1], ab[1][0], ab[1][1], ab[1][2], ab[1][3], bc[2], bc[3]);
            mma16816(acc[3][2], ab[1][0], ab[1][1], ab[1][2], ab[1][3], bc[4], bc[5]);
            mma16816(acc[3][3], ab[1][0], ab[1][1], ab[1][2], ab[1][3], bc[6], bc[7]);
            if (kc + 1 < KITERS) BAR_SYNC_1();
        }
    }

    // ---- epilogue: bias (smem) + float32 stores
    const float* bsm = reinterpret_cast<const float*>(smem + BIAS_OFF);
    const int m_base = m0 + wm + g;
    const int nb = wn + 2 * t;
    #pragma unroll
    for (int j = 0; j < 4; j++) {
        const int cl = nb + j * 8;
        const float b0f = bsm[cl];
        const float b1f = bsm[cl + 1];
        #pragma unroll
        for (int i = 0; i < 4; i++) {
            const size_t r0 = (size_t)(m_base + i * 16);
            float2 v0 = make_float2(acc[i][j][0] + b0f, acc[i][j][1] + b1f);
            float2 v1 = make_float2(acc[i][j][2] + b0f, acc[i][j][3] + b1f);
            *reinterpret_cast<float2*>(out + r0 * OUT_F + n0 + cl) = v0;
            *reinterpret_cast<float2*>(out + (r0 + 8) * OUT_F + n0 + cl) = v1;
        }
    }
}

// ---------------- launch ----------------------------------------------------

extern "C" void kernel_launch(void* const* d_in, const int* in_sizes, int n_in,
                              void* d_out, int out_size) {
    const float* x    = reinterpret_cast<const float*>(d_in[0]);
    const int*   w    = reinterpret_cast<const int*>(d_in[1]);
    const float* sc   = reinterpret_cast<const float*>(d_in[2]);
    const float* bias = reinterpret_cast<const float*>(d_in[3]);
    float*       out  = reinterpret_cast<float*>(d_out);

    prep_kernel<<<XH_BLOCKS + DQ_BLOCKS, 256>>>(x, w, sc);

    cudaFuncSetAttribute(gemm_kernel,
                         cudaFuncAttributeMaxDynamicSharedMemorySize, SM_TOTAL);
    gemm_kernel<<<MTILES * NTILES, 256, SM_TOTAL>>>(bias, out);
}